// round 6
// baseline (speedup 1.0000x reference)
#include <cuda_runtime.h>
#include <math.h>

#define NB 128
#define D_IMG 8192
#define D_LANG 4096
#define KC 128            // k elements per gram chunk
#define KP (KC/2)         // f32x2 k-pairs per chunk = 64
#define NCH_IMG (D_IMG/KC)    // 64
#define NCH_LANG (D_LANG/KC)  // 32
#define GRID (3*NCH_IMG + 3*NCH_LANG)      // 192 + 96 = 288 blocks (2/SM on 148 SMs)
#define GRAM_SMEM (2*KP*64*sizeof(float2)) // 64 KB

// ---------- scratch (static device memory; no allocations) ----------
__device__ float d_part_img[NCH_IMG * NB * NB];
__device__ float d_part_lang[NCH_LANG * NB * NB];
__device__ float d_pre[2 * NB * NB];
__device__ float d_lse[2 * NB];
__device__ unsigned g_count[2];            // zero-init; self-resetting
__device__ volatile unsigned g_phase[2];   // monotonic across replays

#define FFMA2(d, a, b, c) \
    asm("fma.rn.f32x2 %0, %1, %2, %3;" : "=l"(d) : "l"(a), "l"(b), "l"(c))

// load a/b fragments for k-pair KPI (XOR-swizzled layout)
#define LOADAB(KPI, A, B) do {                                   \
    int _g = ((KPI) >> 1) & 15;                                  \
    const unsigned long long* _pa = Au + (KPI) * 64 + (ty ^ _g); \
    const unsigned long long* _pb = Bu + (KPI) * 64 + (tx ^ _g); \
    A[0] = _pa[0];  A[1] = _pa[16]; A[2] = _pa[32]; A[3] = _pa[48]; \
    B[0] = _pb[0];  B[1] = _pb[16]; B[2] = _pb[32]; B[3] = _pb[48]; \
} while (0)

#define FMA16(A, B) do {                                         \
    _Pragma("unroll")                                            \
    for (int ii = 0; ii < 4; ii++)                               \
        _Pragma("unroll")                                        \
        for (int jj = 0; jj < 4; jj++)                           \
            FFMA2(acc[ii][jj], A[ii], B[jj], acc[ii][jj]);       \
} while (0)

// sense-reversing grid barrier; safe because all GRID blocks are co-resident
__device__ __forceinline__ void grid_bar(int id) {
    __syncthreads();
    if (threadIdx.x == 0) {
        __threadfence();
        unsigned p = g_phase[id];
        unsigned old = atomicAdd(&g_count[id], 1);
        if (old == GRID - 1) {
            g_count[id] = 0;
            __threadfence();
            g_phase[id] = p + 1;
        } else {
            while (g_phase[id] == p) {}
        }
        __threadfence();
    }
    __syncthreads();
}

__global__ __launch_bounds__(256, 2) void k_fused(const float* __restrict__ img,
                                                  const float* __restrict__ lang,
                                                  const float* __restrict__ temp,
                                                  float* __restrict__ out) {
    extern __shared__ float2 sm2[];   // phase1: As2[KP][64] | Bs2[KP][64], XOR-swizzled
    int bid = blockIdx.x;
    int t = threadIdx.x;

    // ================= PHASE 1: partial Gram tiles =================
    {
        int m, tp, ch;
        if (bid < 3 * NCH_IMG) { m = 0; tp = bid / NCH_IMG; ch = bid % NCH_IMG; }
        else { int b2 = bid - 3 * NCH_IMG; m = 1; tp = b2 / NCH_LANG; ch = b2 % NCH_LANG; }

        const float* F = m ? lang : img;
        int D = m ? D_LANG : D_IMG;
        float* part = m ? d_part_lang : d_part_img;

        int ti = (tp == 2) ? 1 : 0;   // (0,0),(0,1),(1,1)
        int tj = (tp == 0) ? 0 : 1;
        int ri = ti * 64, rj = tj * 64;
        int k0 = ch * KC;
        bool diag = (ti == tj);

        float2* As2 = sm2;
        float2* Bs2 = sm2 + KP * 64;

        // tile load; layout: slice s (k-pair), row r -> s*64 + (r ^ ((s>>1)&15))
        {
            const float4* Fp = (const float4*)F;
            int D4 = D >> 2;
            int kq0 = k0 >> 2;
#pragma unroll
            for (int l = 0; l < 8; l++) {       // 64 rows x 32 float4 = 2048
                int li = t + 256 * l;
                int row = li >> 5;
                int q = li & 31;
                int rsw = row ^ (q & 15);
                float4 v = Fp[(size_t)(ri + row) * D4 + kq0 + q];
                As2[(2 * q) * 64 + rsw] = make_float2(v.x, v.y);
                As2[(2 * q + 1) * 64 + rsw] = make_float2(v.z, v.w);
            }
            if (!diag) {
#pragma unroll
                for (int l = 0; l < 8; l++) {
                    int li = t + 256 * l;
                    int row = li >> 5;
                    int q = li & 31;
                    int rsw = row ^ (q & 15);
                    float4 v = Fp[(size_t)(rj + row) * D4 + kq0 + q];
                    Bs2[(2 * q) * 64 + rsw] = make_float2(v.x, v.y);
                    Bs2[(2 * q + 1) * 64 + rsw] = make_float2(v.z, v.w);
                }
            }
        }
        __syncthreads();

        const unsigned long long* Au = (const unsigned long long*)As2;
        const unsigned long long* Bu = diag ? Au : (const unsigned long long*)Bs2;
        int tx = t & 15, ty = t >> 4;

        unsigned long long acc[4][4];
#pragma unroll
        for (int ii = 0; ii < 4; ii++)
#pragma unroll
            for (int jj = 0; jj < 4; jj++) acc[ii][jj] = 0ull;

        // software-pipelined: double-buffered register prefetch
        unsigned long long a0[4], b0[4], a1[4], b1[4];
        LOADAB(0, a0, b0);
#pragma unroll 2
        for (int kp = 0; kp < KP; kp += 2) {
            LOADAB(kp + 1, a1, b1);
            FMA16(a0, b0);
            int nxt = (kp + 2 < KP) ? kp + 2 : 0;
            LOADAB(nxt, a0, b0);
            FMA16(a1, b1);
        }

        float g4[4][4];
#pragma unroll
        for (int ii = 0; ii < 4; ii++)
#pragma unroll
            for (int jj = 0; jj < 4; jj++) {
                unsigned long long v = acc[ii][jj];
                g4[ii][jj] = __uint_as_float((unsigned int)v) +
                             __uint_as_float((unsigned int)(v >> 32));
            }

        float* base = part + ch * NB * NB;
#pragma unroll
        for (int ii = 0; ii < 4; ii++)
#pragma unroll
            for (int jj = 0; jj < 4; jj++)
                base[(ri + ty + 16 * ii) * NB + (rj + tx + 16 * jj)] = g4[ii][jj];

        if (tp == 1) {  // mirror (1,0) quadrant via smem-staged transpose
            __syncthreads();
            float* T = (float*)sm2;   // [64][68]
#pragma unroll
            for (int ii = 0; ii < 4; ii++)
#pragma unroll
                for (int jj = 0; jj < 4; jj++)
                    T[(tx + 16 * jj) * 68 + (ty + 16 * ii)] = g4[ii][jj];
            __syncthreads();
#pragma unroll
            for (int l = 0; l < 16; l++) {
                int li = t + 256 * l;
                int cc = li >> 6;
                int rr = li & 63;
                base[(64 + cc) * NB + rr] = T[cc * 68 + rr];
            }
        }
    }

    grid_bar(0);

    // ================= PHASE 2: norms + pre + row lse =================
    float* smf = (float*)sm2;
    float* norm0 = smf;          // [128] image norms
    float* norm1 = smf + 128;    // [128] lang norms
    float* sred  = smf + 256;    // [4] per-warp partials
    if (bid < 256) {
        {
            int mm = t >> 7, j = t & 127;
            const float* part = mm ? d_part_lang : d_part_img;
            int nch = mm ? NCH_LANG : NCH_IMG;
            float s = 0.f;
#pragma unroll 8
            for (int c = 0; c < nch; c++) s += part[c * NB * NB + j * NB + j];
            (mm ? norm1 : norm0)[j] = s;
        }
        float expT = __expf(temp[0]);
        __syncthreads();

        int m = bid >> 7, i = bid & 127;
        if (t < 128) {
            int j = t;
            const float* part = m ? d_part_lang : d_part_img;
            int nch = m ? NCH_LANG : NCH_IMG;
            float g = 0.f;
#pragma unroll 8
            for (int c = 0; c < nch; c++) g += part[c * NB * NB + i * NB + j];
            const float* nrm = m ? norm1 : norm0;
            float sq = nrm[i] + nrm[j] - 2.f * g;
            float pre = (j == i) ? 0.f : -sqrtf(fmaxf(sq, 0.f)) * expT;
            d_pre[m * NB * NB + i * NB + j] = pre;
            float e = __expf(pre);
#pragma unroll
            for (int o = 16; o; o >>= 1) e += __shfl_xor_sync(~0u, e, o);
            if ((j & 31) == 0) sred[j >> 5] = e;
        }
        __syncthreads();
        if (t == 0)
            d_lse[bid] = __logf(sred[0] + sred[1] + sred[2] + sred[3]);
    }

    grid_bar(1);

    // ================= PHASE 3: KL combine + column sum =================
    if (bid < NB && t < NB) {
        int i = t;
        float af = d_pre[i * NB + bid] - d_lse[i];
        float ag = d_pre[NB * NB + i * NB + bid] - d_lse[NB + i];
        float v = __expf(ag) * (ag - af);
#pragma unroll
        for (int o = 16; o; o >>= 1) v += __shfl_xor_sync(~0u, v, o);
        if ((i & 31) == 0) sred[i >> 5] = v;
    }
    __syncthreads();
    if (bid < NB && t == 0)
        out[bid] = sred[0] + sred[1] + sred[2] + sred[3];
}

extern "C" void kernel_launch(void* const* d_in, const int* in_sizes, int n_in,
                              void* d_out, int out_size) {
    const float* img = (const float*)d_in[0];
    const float* lang = (const float*)d_in[1];
    const float* temp = (const float*)d_in[2];
    float* out = (float*)d_out;
    (void)in_sizes; (void)n_in; (void)out_size;

    cudaFuncSetAttribute(k_fused, cudaFuncAttributeMaxDynamicSharedMemorySize,
                         (int)GRAM_SMEM);
    k_fused<<<GRID, 256, GRAM_SMEM>>>(img, lang, temp, out);
}

// round 7
// speedup vs baseline: 1.5591x; 1.5591x over previous
#include <cuda_runtime.h>
#include <math.h>

#define NB 128
#define D_IMG 8192
#define D_LANG 4096
#define KC 256            // k elements per gram chunk
#define KP (KC/2)         // f32x2 k-pairs per chunk = 128
#define NCH_IMG (D_IMG/KC)    // 32
#define NCH_LANG (D_LANG/KC)  // 16
#define GRID (3*NCH_IMG + 3*NCH_LANG)      // 96 + 48 = 144 blocks (1/SM)
#define GRAM_SMEM (2*KP*64*sizeof(float2)) // 128 KB

// ---------- scratch (static device memory; no allocations) ----------
__device__ float d_part_img[NCH_IMG * NB * NB];
__device__ float d_part_lang[NCH_LANG * NB * NB];
__device__ float d_diag[2][NCH_IMG][NB];   // per-chunk Gram diagonals (coalesced)
__device__ float d_pre[2 * NB * NB];
__device__ float d_lse[2 * NB];
__device__ unsigned g_count[2];            // zero-init; self-resetting
__device__ volatile unsigned g_phase[2];   // monotonic across replays

#define FFMA2(d, a, b, c) \
    asm("fma.rn.f32x2 %0, %1, %2, %3;" : "=l"(d) : "l"(a), "l"(b), "l"(c))

// load a/b fragments for k-pair KPI (XOR-swizzled layout)
#define LOADAB(KPI, A, B) do {                                   \
    int _g = ((KPI) >> 1) & 15;                                  \
    const unsigned long long* _pa = Au + (KPI) * 64 + (ty ^ _g); \
    const unsigned long long* _pb = Bu + (KPI) * 64 + (tx ^ _g); \
    A[0] = _pa[0];  A[1] = _pa[16]; A[2] = _pa[32]; A[3] = _pa[48]; \
    B[0] = _pb[0];  B[1] = _pb[16]; B[2] = _pb[32]; B[3] = _pb[48]; \
} while (0)

#define FMA16(A, B) do {                                         \
    _Pragma("unroll")                                            \
    for (int ii = 0; ii < 4; ii++)                               \
        _Pragma("unroll")                                        \
        for (int jj = 0; jj < 4; jj++)                           \
            FFMA2(acc[ii][jj], A[ii], B[jj], acc[ii][jj]);       \
} while (0)

// sense-reversing grid barrier; safe because all GRID blocks are co-resident
__device__ __forceinline__ void grid_bar(int id) {
    __syncthreads();
    if (threadIdx.x == 0) {
        __threadfence();
        unsigned p = g_phase[id];
        unsigned old = atomicAdd(&g_count[id], 1);
        if (old == GRID - 1) {
            g_count[id] = 0;
            __threadfence();
            g_phase[id] = p + 1;
        } else {
            while (g_phase[id] == p) {}
        }
        __threadfence();
    }
    __syncthreads();
}

__global__ __launch_bounds__(256, 1) void k_fused(const float* __restrict__ img,
                                                  const float* __restrict__ lang,
                                                  const float* __restrict__ temp,
                                                  float* __restrict__ out) {
    extern __shared__ float2 sm2[];   // phase1: As2[KP][64] | Bs2[KP][64], XOR-swizzled
    int bid = blockIdx.x;
    int t = threadIdx.x;

    // ================= PHASE 1: partial Gram tiles =================
    {
        int m, tp, ch;
        if (bid < 3 * NCH_IMG) { m = 0; tp = bid / NCH_IMG; ch = bid % NCH_IMG; }
        else { int b2 = bid - 3 * NCH_IMG; m = 1; tp = b2 / NCH_LANG; ch = b2 % NCH_LANG; }

        const float* F = m ? lang : img;
        int D = m ? D_LANG : D_IMG;
        float* part = m ? d_part_lang : d_part_img;

        int ti = (tp == 2) ? 1 : 0;   // (0,0),(0,1),(1,1)
        int tj = (tp == 0) ? 0 : 1;
        int ri = ti * 64, rj = tj * 64;
        int k0 = ch * KC;
        bool diag = (ti == tj);

        float2* As2 = sm2;
        float2* Bs2 = sm2 + KP * 64;

        // tile load; layout: slice s (k-pair), row r -> s*64 + (r ^ ((s>>1)&15))
        {
            const float4* Fp = (const float4*)F;
            int D4 = D >> 2;
            int kq0 = k0 >> 2;
#pragma unroll
            for (int l = 0; l < 16; l++) {      // 64 rows x 64 float4
                int li = t + 256 * l;
                int row = li >> 6;
                int q = li & 63;
                int rsw = row ^ (q & 15);
                float4 v = Fp[(size_t)(ri + row) * D4 + kq0 + q];
                As2[(2 * q) * 64 + rsw] = make_float2(v.x, v.y);
                As2[(2 * q + 1) * 64 + rsw] = make_float2(v.z, v.w);
            }
            if (!diag) {
#pragma unroll
                for (int l = 0; l < 16; l++) {
                    int li = t + 256 * l;
                    int row = li >> 6;
                    int q = li & 63;
                    int rsw = row ^ (q & 15);
                    float4 v = Fp[(size_t)(rj + row) * D4 + kq0 + q];
                    Bs2[(2 * q) * 64 + rsw] = make_float2(v.x, v.y);
                    Bs2[(2 * q + 1) * 64 + rsw] = make_float2(v.z, v.w);
                }
            }
        }
        __syncthreads();

        const unsigned long long* Au = (const unsigned long long*)As2;
        const unsigned long long* Bu = diag ? Au : (const unsigned long long*)Bs2;
        int tx = t & 15, ty = t >> 4;

        unsigned long long acc[4][4];
#pragma unroll
        for (int ii = 0; ii < 4; ii++)
#pragma unroll
            for (int jj = 0; jj < 4; jj++) acc[ii][jj] = 0ull;

        // software-pipelined: double-buffered register prefetch (no wraparound)
        unsigned long long a0[4], b0[4], a1[4], b1[4];
        LOADAB(0, a0, b0);
#pragma unroll 2
        for (int kp = 0; kp < KP - 2; kp += 2) {
            LOADAB(kp + 1, a1, b1);
            FMA16(a0, b0);
            LOADAB(kp + 2, a0, b0);
            FMA16(a1, b1);
        }
        LOADAB(KP - 1, a1, b1);
        FMA16(a0, b0);
        FMA16(a1, b1);

        float g4[4][4];
#pragma unroll
        for (int ii = 0; ii < 4; ii++)
#pragma unroll
            for (int jj = 0; jj < 4; jj++) {
                unsigned long long v = acc[ii][jj];
                g4[ii][jj] = __uint_as_float((unsigned int)v) +
                             __uint_as_float((unsigned int)(v >> 32));
            }

        float* base = part + ch * NB * NB;
#pragma unroll
        for (int ii = 0; ii < 4; ii++)
#pragma unroll
            for (int jj = 0; jj < 4; jj++)
                base[(ri + ty + 16 * ii) * NB + (rj + tx + 16 * jj)] = g4[ii][jj];

        if (diag && tx == ty) {   // dump per-chunk Gram diagonal (row==col elems)
#pragma unroll
            for (int ii = 0; ii < 4; ii++)
                d_diag[m][ch][ri + ty + 16 * ii] = g4[ii][ii];
        }

        if (tp == 1) {  // mirror (1,0) quadrant via smem-staged transpose
            __syncthreads();
            float* T = (float*)sm2;   // [64][68]
#pragma unroll
            for (int ii = 0; ii < 4; ii++)
#pragma unroll
                for (int jj = 0; jj < 4; jj++)
                    T[(tx + 16 * jj) * 68 + (ty + 16 * ii)] = g4[ii][jj];
            __syncthreads();
#pragma unroll
            for (int l = 0; l < 16; l++) {
                int li = t + 256 * l;
                int cc = li >> 6;
                int rr = li & 63;
                base[(64 + cc) * NB + rr] = T[cc * 68 + rr];
            }
        }
    }

    grid_bar(0);

    // ================= PHASE 2: norms + pre + row lse =================
    float* smf = (float*)sm2;
    float* norm0 = smf;          // [128] image norms
    float* norm1 = smf + 128;    // [128] lang norms
    float* sred  = smf + 256;    // [8] per-warp partials
    {
        int mm = t >> 7, j = t & 127;
        int nch = mm ? NCH_LANG : NCH_IMG;
        float s = 0.f;
#pragma unroll 8
        for (int c = 0; c < nch; c++) s += d_diag[mm][c][j];   // coalesced
        (mm ? norm1 : norm0)[j] = s;
    }
    float expT = __expf(temp[0]);
    __syncthreads();

    int half = t >> 7, j = t & 127;
    int r = half ? bid + GRID : bid;            // rows 0-143 and 144-255
    bool valid = half ? (bid < 256 - GRID) : true;
    if (valid) {
        int m = r >> 7, i = r & 127;
        const float* part = m ? d_part_lang : d_part_img;
        int nch = m ? NCH_LANG : NCH_IMG;
        float g = 0.f;
#pragma unroll 8
        for (int c = 0; c < nch; c++) g += part[c * NB * NB + i * NB + j];
        const float* nrm = m ? norm1 : norm0;
        float sq = nrm[i] + nrm[j] - 2.f * g;
        float pre = (j == i) ? 0.f : -sqrtf(fmaxf(sq, 0.f)) * expT;
        d_pre[m * NB * NB + i * NB + j] = pre;
        float e = __expf(pre);
#pragma unroll
        for (int o = 16; o; o >>= 1) e += __shfl_xor_sync(~0u, e, o);
        if ((j & 31) == 0) sred[t >> 5] = e;
    }
    __syncthreads();
    if (valid && j == 0) {
        int base = half * 4;
        float s = sred[base] + sred[base + 1] + sred[base + 2] + sred[base + 3];
        d_lse[r] = __logf(s);
    }

    grid_bar(1);

    // ================= PHASE 3: KL combine + column sum =================
    if (bid < NB && t < NB) {
        int i = t;
        float af = d_pre[i * NB + bid] - d_lse[i];
        float ag = d_pre[NB * NB + i * NB + bid] - d_lse[NB + i];
        float v = __expf(ag) * (ag - af);
#pragma unroll
        for (int o = 16; o; o >>= 1) v += __shfl_xor_sync(~0u, v, o);
        if ((i & 31) == 0) sred[i >> 5] = v;
    }
    __syncthreads();
    if (bid < NB && t == 0)
        out[bid] = sred[0] + sred[1] + sred[2] + sred[3];
}

extern "C" void kernel_launch(void* const* d_in, const int* in_sizes, int n_in,
                              void* d_out, int out_size) {
    const float* img = (const float*)d_in[0];
    const float* lang = (const float*)d_in[1];
    const float* temp = (const float*)d_in[2];
    float* out = (float*)d_out;
    (void)in_sizes; (void)n_in; (void)out_size;

    cudaFuncSetAttribute(k_fused, cudaFuncAttributeMaxDynamicSharedMemorySize,
                         (int)GRAM_SMEM);
    k_fused<<<GRID, 256, GRAM_SMEM>>>(img, lang, temp, out);
}